// round 11
// baseline (speedup 1.0000x reference)
#include <cuda_runtime.h>
#include <cuda_fp16.h>
#include <math.h>
#include <cstdint>

// Problem constants
#define B 4
#define C 64
#define NA 25
#define H 64
#define W 64
#define S 320        // H*U
#define NCHUNK 320   // chunks of 64 floats along w
#define D_TOT 20480  // feature dim
#define BSTRIDE 6553600
#define CSTRIDE 102400
#define NSTRIDE 4096
#define SK 16                       // split-K for scores
#define KSTEPS (D_TOT / SK / 64)    // 20 K-blocks of 64 per split
#define NCONV 4                     // conv_qk pipeline chunks
#define CPC (NCHUNK / NCONV)        // 80 64-float chunks per conv piece

typedef unsigned long long u64;

// ---- scratch (device globals; no allocations allowed) ----
__device__ float g_rq[B * S];
__device__ float g_rk[B * S];
__device__ float g_normp[2][NCONV][B * S];         // partial sq-norms per conv chunk
__device__ float g_attp[(size_t)SK * B * S * S];   // split-K partial scores (f32, raw q.k)
__device__ __half g_attb[(size_t)B * S * S];       // softmax probs (f16)
__device__ __half g_qb[(size_t)B * S * D_TOT];
__device__ __half g_kb[(size_t)B * S * D_TOT];
__device__ __half g_vb[(size_t)B * S * D_TOT];

// original-layout address of (b, s, chunk ck, w=0)
__device__ __forceinline__ size_t elem_base(int b, int s, int ck) {
    int h = s / 5, uu = s - h * 5;
    int c = ck / 5, vv = ck - c * 5;
    return (size_t)b * BSTRIDE + (size_t)c * CSTRIDE + (size_t)(uu * 5 + vv) * NSTRIDE + (size_t)h * W;
}

// ---- PTX helpers (sm_80-level: valid at virtual target sm_103) ----
__device__ __forceinline__ uint32_t smem_u32(const void* p) {
    uint32_t a;
    asm("{ .reg .u64 t; cvta.to.shared.u64 t, %1; cvt.u32.u64 %0, t; }" : "=r"(a) : "l"(p));
    return a;
}
__device__ __forceinline__ void cpa16(uint32_t dst, const void* src) {
    asm volatile("{ .reg .u64 g; cvta.to.global.u64 g, %1; cp.async.cg.shared.global [%0], [g], 16; }"
                 :: "r"(dst), "l"(src) : "memory");
}
#define CP_COMMIT() asm volatile("cp.async.commit_group;" ::: "memory")
#define CP_WAIT0()  asm volatile("cp.async.wait_group 0;" ::: "memory")
#define CP_WAIT1()  asm volatile("cp.async.wait_group 1;" ::: "memory")

__device__ __forceinline__ void ldm4(uint32_t* r, uint32_t addr) {
    asm volatile("ldmatrix.sync.aligned.m8n8.x4.shared.b16 {%0,%1,%2,%3}, [%4];"
                 : "=r"(r[0]), "=r"(r[1]), "=r"(r[2]), "=r"(r[3]) : "r"(addr));
}
__device__ __forceinline__ void ldm4t(uint32_t* r, uint32_t addr) {
    asm volatile("ldmatrix.sync.aligned.m8n8.x4.trans.shared.b16 {%0,%1,%2,%3}, [%4];"
                 : "=r"(r[0]), "=r"(r[1]), "=r"(r[2]), "=r"(r[3]) : "r"(addr));
}
__device__ __forceinline__ void mma_f16(float* d, const uint32_t* a, const uint32_t* b) {
    asm volatile("mma.sync.aligned.m16n8k16.row.col.f32.f16.f16.f32 "
                 "{%0,%1,%2,%3}, {%4,%5,%6,%7}, {%8,%9}, {%0,%1,%2,%3};"
                 : "+f"(d[0]), "+f"(d[1]), "+f"(d[2]), "+f"(d[3])
                 : "r"(a[0]), "r"(a[1]), "r"(a[2]), "r"(a[3]), "r"(b[0]), "r"(b[1]));
}

// ---------------------------------------------------------------------------
// K1a: gather + f16 convert of Q,K for ONE d-chunk (D/4) + partial sq-norms.
// grid (B*S, 2), 256 threads.  Chunk g feeds scores split-group g.
// ---------------------------------------------------------------------------
__global__ __launch_bounds__(256) void conv_qk_kernel(const float* __restrict__ q,
                                                      const float* __restrict__ k,
                                                      int chunk) {
    int row = blockIdx.x;
    int which = blockIdx.y;
    const float* src = which ? k : q;
    __half* dstb = which ? g_kb : g_qb;
    int b = row / S, s = row - b * S;
    int ck0 = chunk * CPC;

    uint2* drow = (uint2*)(dstb + (size_t)row * D_TOT);
    float acc = 0.f;
    for (int i = threadIdx.x; i < CPC * 16; i += 256) {
        int ck = ck0 + (i >> 4), f4 = i & 15;
        const float4 x = *(const float4*)(src + elem_base(b, s, ck) + f4 * 4);
        acc += x.x * x.x + x.y * x.y + x.z * x.z + x.w * x.w;
        __half2 p0 = __floats2half2_rn(x.x, x.y);
        __half2 p1 = __floats2half2_rn(x.z, x.w);
        uint2 wv;
        *reinterpret_cast<__half2*>(&wv.x) = p0;
        *reinterpret_cast<__half2*>(&wv.y) = p1;
        drow[ck * 16 + f4] = wv;
    }
    __shared__ float red[256];
    red[threadIdx.x] = acc;
    __syncthreads();
    for (int off = 128; off; off >>= 1) {
        if (threadIdx.x < off) red[threadIdx.x] += red[threadIdx.x + off];
        __syncthreads();
    }
    if (threadIdx.x == 0) g_normp[which][chunk][row] = red[0];
}

// K1c: reduce partial norms -> inverse norms.  grid 10 x 256.
__global__ __launch_bounds__(256) void norm_reduce_kernel() {
    int idx = blockIdx.x * 256 + threadIdx.x;
    if (idx < 2 * B * S) {
        int which = idx / (B * S), row = idx - which * (B * S);
        float sum = 0.f;
        #pragma unroll
        for (int c = 0; c < NCONV; c++) sum += g_normp[which][c][row];
        float r = 1.f / fmaxf(sqrtf(sum), 1e-12f);
        (which ? g_rk : g_rq)[row] = r;
    }
}

// ---------------------------------------------------------------------------
// K1b: gather + f16 convert of V only (no norms).  grid B*S, 256 threads.
// Runs on a side stream, overlapped with conv_qk/scores.
// ---------------------------------------------------------------------------
__global__ __launch_bounds__(256) void conv_v_kernel(const float* __restrict__ v) {
    int row = blockIdx.x;
    int b = row / S, s = row - b * S;
    uint2* drow = (uint2*)(g_vb + (size_t)row * D_TOT);
    for (int i = threadIdx.x; i < NCHUNK * 16; i += 256) {
        int ck = i >> 4, f4 = i & 15;
        const float4 x = *(const float4*)(v + elem_base(b, s, ck) + f4 * 4);
        __half2 p0 = __floats2half2_rn(x.x, x.y);
        __half2 p1 = __floats2half2_rn(x.z, x.w);
        uint2 wv;
        *reinterpret_cast<__half2*>(&wv.x) = p0;
        *reinterpret_cast<__half2*>(&wv.y) = p1;
        drow[i] = wv;
    }
}

// ---------------------------------------------------------------------------
// K2: scores = Q K^T (raw, norms applied later in softmax) via mma.sync f16.
// Tile 128x128, K-blocks of 64.  One launch = 4 consecutive splits (sgroup).
// grid (6 pairs, 4 splits, B), 256 threads, 64KB dynamic smem.
// ---------------------------------------------------------------------------
#define SC_A0 0
#define SC_A1 16384
#define SC_B0 32768
#define SC_B1 49152
#define SC_SMEM 65536

__global__ __launch_bounds__(256) void scores_mma(int sgroup) {
    extern __shared__ char sm[];
    uint32_t sb = smem_u32(sm);
    const int MI[6] = {0, 1, 1, 2, 2, 2};
    const int NJ[6] = {0, 0, 1, 0, 1, 2};
    int pair = blockIdx.x, split = sgroup * 4 + blockIdx.y, b = blockIdx.z;
    int s0 = MI[pair] * 128, t0 = NJ[pair] * 128;
    int tid = threadIdx.x, l = tid & 31, wid = tid >> 5;
    int wm = wid >> 2, wn = wid & 3;    // warp grid 2 (M) x 4 (N)
    int d_base = split * (D_TOT / SK);

    const __half* qrow = g_qb + (size_t)b * S * D_TOT;
    const __half* krow = g_kb + (size_t)b * S * D_TOT;

    float acc[4][4][4];
    #pragma unroll
    for (int f = 0; f < 4; f++)
        #pragma unroll
        for (int nf = 0; nf < 4; nf++)
            #pragma unroll
            for (int e = 0; e < 4; e++) acc[f][nf][e] = 0.f;

    const uint32_t AOF[2] = {SC_A0, SC_A1}, BOF[2] = {SC_B0, SC_B1};

    // fill step 0
    {
        int d0 = d_base;
        #pragma unroll
        for (int j = 0; j < 4; j++) {
            int idx = tid + 256 * j, r = idx >> 3, g = idx & 7;
            int s = s0 + r; if (s >= S) s = S - 1;
            cpa16(sb + SC_A0 + r * 128 + ((g ^ (r & 7)) << 4), qrow + (size_t)s * D_TOT + d0 + g * 8);
        }
        #pragma unroll
        for (int j = 0; j < 4; j++) {
            int idx = tid + 256 * j, r = idx >> 3, g = idx & 7;
            int t = t0 + r; if (t >= S) t = S - 1;
            cpa16(sb + SC_B0 + r * 128 + ((g ^ (r & 7)) << 4), krow + (size_t)t * D_TOT + d0 + g * 8);
        }
        CP_COMMIT();
    }

    for (int step = 0; step < KSTEPS; step++) {
        int buf = step & 1;
        if (step + 1 < KSTEPS) {
            int d0 = d_base + (step + 1) * 64;
            uint32_t a_of = AOF[buf ^ 1], b_of = BOF[buf ^ 1];
            #pragma unroll
            for (int j = 0; j < 4; j++) {
                int idx = tid + 256 * j, r = idx >> 3, g = idx & 7;
                int s = s0 + r; if (s >= S) s = S - 1;
                cpa16(sb + a_of + r * 128 + ((g ^ (r & 7)) << 4), qrow + (size_t)s * D_TOT + d0 + g * 8);
            }
            #pragma unroll
            for (int j = 0; j < 4; j++) {
                int idx = tid + 256 * j, r = idx >> 3, g = idx & 7;
                int t = t0 + r; if (t >= S) t = S - 1;
                cpa16(sb + b_of + r * 128 + ((g ^ (r & 7)) << 4), krow + (size_t)t * D_TOT + d0 + g * 8);
            }
            CP_COMMIT();
            CP_WAIT1();
        } else {
            CP_WAIT0();
        }
        __syncthreads();
        uint32_t Ab = sb + AOF[buf], Bb = sb + BOF[buf];
        #pragma unroll
        for (int kk = 0; kk < 4; kk++) {
            uint32_t af[4][4], bfr[2][4];
            #pragma unroll
            for (int f = 0; f < 4; f++) {
                int rowA = wm * 64 + f * 16 + (l & 15);
                int g = 2 * kk + (l >> 4);
                ldm4(af[f], Ab + rowA * 128 + ((g ^ (l & 7)) << 4));
            }
            #pragma unroll
            for (int h = 0; h < 2; h++) {
                int rowB = wn * 32 + h * 16 + (l & 7) + ((l >> 4) << 3);
                int g = 2 * kk + ((l >> 3) & 1);
                ldm4(bfr[h], Bb + rowB * 128 + ((g ^ (rowB & 7)) << 4));
            }
            #pragma unroll
            for (int f = 0; f < 4; f++)
                #pragma unroll
                for (int nf = 0; nf < 4; nf++)
                    mma_f16(acc[f][nf], af[f], &bfr[nf >> 1][(nf & 1) * 2]);
        }
        __syncthreads();
    }

    // epilogue: store raw split partials (norms applied in softmax)
    float* outp = g_attp + (size_t)split * (B * S * S) + (size_t)b * S * S;
    #pragma unroll
    for (int f = 0; f < 4; f++) {
        int r0 = s0 + wm * 64 + f * 16 + (l >> 2);
        #pragma unroll
        for (int half = 0; half < 2; half++) {
            int s = r0 + half * 8;
            if (s < S) {
                #pragma unroll
                for (int nf = 0; nf < 4; nf++) {
                    int t = t0 + wn * 32 + nf * 8 + (l & 3) * 2;
                    if (t < S) {
                        float2 o;
                        o.x = acc[f][nf][half * 2 + 0];
                        o.y = acc[f][nf][half * 2 + 1];
                        *(float2*)(outp + (size_t)s * S + t) = o;
                    }
                }
            }
        }
    }
}

// ---------------------------------------------------------------------------
// K3: split-K reduce + norm scale + causal softmax -> f16 probabilities.
// grid B*S, 320 threads.
// ---------------------------------------------------------------------------
__global__ __launch_bounds__(S) void softmax_kernel() {
    int row = blockIdx.x;
    int b = row / S;
    int s = row - b * S;
    int tid = threadIdx.x;
    __shared__ float red[10];

    float x;
    if (tid <= s) {
        x = 0.f;
        #pragma unroll
        for (int sp = 0; sp < SK; sp++)
            x += g_attp[(size_t)sp * (B * S * S) + (size_t)row * S + tid];
        x *= g_rq[row] * g_rk[b * S + tid];   // cosine-normalize here
    } else {
        x = -1e30f;
    }
    float m = x;
    #pragma unroll
    for (int o = 16; o; o >>= 1) m = fmaxf(m, __shfl_xor_sync(0xffffffffu, m, o));
    if ((tid & 31) == 0) red[tid >> 5] = m;
    __syncthreads();
    float mall = red[0];
    #pragma unroll
    for (int i = 1; i < 10; i++) mall = fmaxf(mall, red[i]);

    float e = (tid <= s) ? expf(x - mall) : 0.f;
    float ssum = e;
    #pragma unroll
    for (int o = 16; o; o >>= 1) ssum += __shfl_xor_sync(0xffffffffu, ssum, o);
    __syncthreads();
    if ((tid & 31) == 0) red[tid >> 5] = ssum;
    __syncthreads();
    float tot = 0.f;
    #pragma unroll
    for (int i = 0; i < 10; i++) tot += red[i];

    g_attb[(size_t)row * S + tid] = __float2half(e / tot);
}

// ---------------------------------------------------------------------------
// K4: out = att @ V + residual via mma.sync f16.  Tile M=64(s) x N=128(d),
// K = t-blocks of 64 (causal: stile+1 blocks).  2-stage, 48KB smem -> 4 CTAs/SM.
// grid (160, 5, B), 256 threads.
// ---------------------------------------------------------------------------
#define OU_A0 0
#define OU_A1 8192
#define OU_B0 16384
#define OU_B1 32768
#define OU_SMEM 49152

__global__ __launch_bounds__(256) void out_mma(const float* __restrict__ v,
                                               float* __restrict__ out) {
    extern __shared__ char sm[];
    uint32_t sb = smem_u32(sm);
    int ckp = blockIdx.x, stile = blockIdx.y, b = blockIdx.z;
    int s0 = stile * 64, n0 = ckp * 128;
    int tid = threadIdx.x, l = tid & 31, wid = tid >> 5;
    int wm = wid >> 2, wn = wid & 3;    // warp grid 2 (M: 32 rows) x 4 (N: 32 cols)
    int nblocks = stile + 1;

    const __half* pb = g_attb + (size_t)b * S * S;
    const __half* vb = g_vb + (size_t)b * S * D_TOT;

    float acc[2][4][4];
    #pragma unroll
    for (int f = 0; f < 2; f++)
        #pragma unroll
        for (int nf = 0; nf < 4; nf++)
            #pragma unroll
            for (int e = 0; e < 4; e++) acc[f][nf][e] = 0.f;

    const uint32_t AOF[2] = {OU_A0, OU_A1}, BOF[2] = {OU_B0, OU_B1};

    // fill block 0: A = att tile 64x64 (128B rows), B = V tile 64x128 (256B rows)
    {
        #pragma unroll
        for (int j = 0; j < 2; j++) {
            int idx = tid + 256 * j, r = idx >> 3, g = idx & 7;
            cpa16(sb + OU_A0 + r * 128 + ((g ^ (r & 7)) << 4), pb + (size_t)(s0 + r) * S + g * 8);
        }
        #pragma unroll
        for (int j = 0; j < 4; j++) {
            int idx = tid + 256 * j, r = idx >> 4, g = idx & 15;
            cpa16(sb + OU_B0 + r * 256 + ((g ^ (r & 7)) << 4), vb + (size_t)r * D_TOT + n0 + g * 8);
        }
        CP_COMMIT();
    }

    for (int tt = 0; tt < nblocks; tt++) {
        int buf = tt & 1;
        if (tt + 1 < nblocks) {
            int t1 = (tt + 1) * 64;
            uint32_t a_of = AOF[buf ^ 1], b_of = BOF[buf ^ 1];
            #pragma unroll
            for (int j = 0; j < 2; j++) {
                int idx = tid + 256 * j, r = idx >> 3, g = idx & 7;
                cpa16(sb + a_of + r * 128 + ((g ^ (r & 7)) << 4), pb + (size_t)(s0 + r) * S + t1 + g * 8);
            }
            #pragma unroll
            for (int j = 0; j < 4; j++) {
                int idx = tid + 256 * j, r = idx >> 4, g = idx & 15;
                cpa16(sb + b_of + r * 256 + ((g ^ (r & 7)) << 4), vb + (size_t)(t1 + r) * D_TOT + n0 + g * 8);
            }
            CP_COMMIT();
            CP_WAIT1();
        } else {
            CP_WAIT0();
        }
        __syncthreads();
        uint32_t Ab = sb + AOF[buf], Bb = sb + BOF[buf];
        #pragma unroll
        for (int kk = 0; kk < 4; kk++) {
            uint32_t af[2][4], bfr[2][4];
            #pragma unroll
            for (int f = 0; f < 2; f++) {
                int rowA = wm * 32 + f * 16 + (l & 15);
                int g = 2 * kk + (l >> 4);
                ldm4(af[f], Ab + rowA * 128 + ((g ^ (l & 7)) << 4));
            }
            #pragma unroll
            for (int h = 0; h < 2; h++) {
                int rowB = kk * 16 + (l & 15);
                int g = wn * 4 + h * 2 + (l >> 4);
                ldm4t(bfr[h], Bb + rowB * 256 + ((g ^ (rowB & 7)) << 4));
            }
            #pragma unroll
            for (int f = 0; f < 2; f++)
                #pragma unroll
                for (int nf = 0; nf < 4; nf++)
                    mma_f16(acc[f][nf], af[f], &bfr[nf >> 1][(nf & 1) * 2]);
        }
        __syncthreads();
    }

    // epilogue: residual add (fp32 token_v) + store to original layout
    #pragma unroll
    for (int f = 0; f < 2; f++) {
        #pragma unroll
        for (int half = 0; half < 2; half++) {
            int s = s0 + wm * 32 + f * 16 + (l >> 2) + half * 8;
            #pragma unroll
            for (int nf = 0; nf < 4; nf++) {
                int d = n0 + wn * 32 + nf * 8 + (l & 3) * 2;
                int ck = d >> 6, w = d & 63;
                size_t g = elem_base(b, s, ck) + w;
                float2 vv = *(const float2*)(v + g);
                float2 o;
                o.x = acc[f][nf][half * 2 + 0] + vv.x;
                o.y = acc[f][nf][half * 2 + 1] + vv.y;
                *(float2*)(out + g) = o;
            }
        }
    }
}

// ---------------------------------------------------------------------------
extern "C" void kernel_launch(void* const* d_in, const int* in_sizes, int n_in,
                              void* d_out, int out_size) {
    const float* q = (const float*)d_in[0];
    const float* k = (const float*)d_in[1];
    const float* v = (const float*)d_in[2];
    float* out = (float*)d_out;

    static bool init_done = false;
    static cudaStream_t s2, s3;
    static cudaEvent_t ev_fork, ev_vdone, ev_scdone, ev_c[NCONV];
    if (!init_done) {
        cudaFuncSetAttribute(scores_mma, cudaFuncAttributeMaxDynamicSharedMemorySize, SC_SMEM);
        cudaFuncSetAttribute(out_mma, cudaFuncAttributeMaxDynamicSharedMemorySize, OU_SMEM);
        cudaStreamCreateWithFlags(&s2, cudaStreamNonBlocking);
        cudaStreamCreateWithFlags(&s3, cudaStreamNonBlocking);
        cudaEventCreateWithFlags(&ev_fork, cudaEventDisableTiming);
        cudaEventCreateWithFlags(&ev_vdone, cudaEventDisableTiming);
        cudaEventCreateWithFlags(&ev_scdone, cudaEventDisableTiming);
        for (int i = 0; i < NCONV; i++) cudaEventCreateWithFlags(&ev_c[i], cudaEventDisableTiming);
        init_done = true;
    }

    // fork side streams
    cudaEventRecord(ev_fork, 0);
    cudaStreamWaitEvent(s2, ev_fork, 0);
    cudaStreamWaitEvent(s3, ev_fork, 0);

    // s2: V conversion, independent until out_mma
    conv_v_kernel<<<B * S, 256, 0, s2>>>(v);

    // main: conv_qk chunks; s3: scores group g starts when chunk g lands
    for (int g = 0; g < NCONV; g++) {
        conv_qk_kernel<<<dim3(B * S, 2), 256>>>(q, k, g);
        cudaEventRecord(ev_c[g], 0);
        cudaStreamWaitEvent(s3, ev_c[g], 0);
        scores_mma<<<dim3(6, 4, B), 256, SC_SMEM, s3>>>(g);
    }
    norm_reduce_kernel<<<10, 256>>>();   // main; after all conv chunks

    // join scores -> softmax (main)
    cudaEventRecord(ev_scdone, s3);
    cudaStreamWaitEvent(0, ev_scdone, 0);
    softmax_kernel<<<B * S, S>>>();

    // join conv_v -> out_mma
    cudaEventRecord(ev_vdone, s2);
    cudaStreamWaitEvent(0, ev_vdone, 0);
    out_mma<<<dim3(160, 5, B), 256, OU_SMEM>>>(v, out);
}